// round 12
// baseline (speedup 1.0000x reference)
#include <cuda_runtime.h>
#include <cuda_fp16.h>
#include <cstdint>

#define BATCH 128
#define SEQ   512
#define HID   1024
#define H2    2048
#define EMB   512
#define VOCAB 32000
#define KG    3584          /* 2048 ctx + 512 emb + 1024 hidden */
#define NG    4096
#define K1G   2560          /* W_ih K extent */
#define GSPLIT 8
#define ASPL  2             /* attention s-splits */
#define PADA  40
#define PADB  40
#define DEPTH 3
#define A_STG_B (128 * PADA * 2)
#define B_STG_B (128 * PADB * 4)
#define STG_B   (A_STG_B + B_STG_B)
#define GEMM_SMEM (DEPTH * STG_B)           /* 92160 -> 2 CTAs/SM */

__device__ float  g_ctx_part[ASPL * BATCH * H2];
__device__ float  g_zpart[ASPL * BATCH];
__device__ __half g_act16[BATCH * KG];
__device__ __half g_h16[BATCH * HID];
__device__ float  g_gates_part[GSPLIT * BATCH * NG];

// ---------------------------------------------------------------------------
__device__ __forceinline__ uint32_t smem_u32(const void* p) {
    return (uint32_t)__cvta_generic_to_shared(p);
}
__device__ __forceinline__ void cpa16(uint32_t dst, const void* src) {
    asm volatile("cp.async.cg.shared.global [%0], [%1], 16;\n" :: "r"(dst), "l"(src));
}
#define CPA_COMMIT() asm volatile("cp.async.commit_group;\n" ::: "memory")
#define CPA_WAIT(n)  asm volatile("cp.async.wait_group %0;\n" :: "n"(n) : "memory")

__device__ __forceinline__ void ldm_x4(uint32_t* r, const __half* p) {
    uint32_t a = smem_u32(p);
    asm volatile("ldmatrix.sync.aligned.m8n8.x4.shared.b16 {%0,%1,%2,%3}, [%4];\n"
                 : "=r"(r[0]), "=r"(r[1]), "=r"(r[2]), "=r"(r[3]) : "r"(a));
}
__device__ __forceinline__ void mma_f16(float* d, const uint32_t* a, const uint32_t* b) {
    asm volatile("mma.sync.aligned.m16n8k16.row.col.f32.f16.f16.f32 "
                 "{%0,%1,%2,%3}, {%4,%5,%6,%7}, {%8,%9}, {%0,%1,%2,%3};\n"
                 : "+f"(d[0]), "+f"(d[1]), "+f"(d[2]), "+f"(d[3])
                 : "r"(a[0]), "r"(a[1]), "r"(a[2]), "r"(a[3]), "r"(b[0]), "r"(b[1]));
}
__device__ __forceinline__ uint32_t pk(float a, float b) {
    __half2 h = __floats2half2_rn(a, b);
    return *reinterpret_cast<uint32_t*>(&h);
}

// ===========================================================================
// attention: grid (BATCH, ASPL), 128 threads (4 warps), 2 CTAs/SM.
// Inner loop identical to R5 (register double-buffered rows, no max-shift —
// energies relu-bounded so exp is safe). Each CTA covers 256 s-rows; warp w
// owns s = s0 + w, w+4, ... Unnormalized partial ctx + Z per (split, b).
// ===========================================================================
__device__ __forceinline__ void attn_step(
    const float4* __restrict__ w2v4, int lane, const float4 v[16],
    float hb, float& Zw, float4 acc[16])
{
    float pr = 0.f;
    #pragma unroll
    for (int i = 0; i < 16; i++) {
        float4 w = w2v4[lane + 32 * i];
        pr += v[i].x * w.x + v[i].y * w.y + v[i].z * w.z + v[i].w * w.w;
    }
    #pragma unroll
    for (int o = 16; o > 0; o >>= 1) pr += __shfl_xor_sync(0xffffffffu, pr, o);
    float wg = __expf(fmaxf(pr + hb, 0.f));
    Zw += wg;
    #pragma unroll
    for (int i = 0; i < 16; i++) {
        acc[i].x += wg * v[i].x; acc[i].y += wg * v[i].y;
        acc[i].z += wg * v[i].z; acc[i].w += wg * v[i].w;
    }
}

__global__ __launch_bounds__(128, 2) void attn_kernel(
    const float* __restrict__ enc, const float* __restrict__ hidden,
    const float* __restrict__ W_e, const float* __restrict__ b_e)
{
    __shared__ float s_w2[H2], s_acc[H2];
    __shared__ float s_red[4], s_z[4];
    __shared__ float s_hb;

    int b = blockIdx.x, split = blockIdx.y, t = threadIdx.x;
    int warp = t >> 5, lane = t & 31;

    for (int j = t; j < H2; j += 128) { s_w2[j] = W_e[HID + j]; s_acc[j] = 0.f; }

    float p = 0.f;
    for (int j = t; j < HID; j += 128) p += hidden[b * HID + j] * W_e[j];
    #pragma unroll
    for (int o = 16; o > 0; o >>= 1) p += __shfl_xor_sync(0xffffffffu, p, o);
    if (lane == 0) s_red[warp] = p;
    __syncthreads();
    if (t == 0) s_hb = s_red[0] + s_red[1] + s_red[2] + s_red[3] + b_e[0];
    __syncthreads();
    float hb = s_hb;

    const float4* w2v4 = (const float4*)s_w2;

    float4 acc[16];
    #pragma unroll
    for (int i = 0; i < 16; i++) acc[i] = make_float4(0.f, 0.f, 0.f, 0.f);
    float Zw = 0.f;

    int s0 = split * (SEQ / ASPL);
    int s1 = s0 + (SEQ / ASPL);

    float4 va[16], vb[16];
    {
        const float4* row = (const float4*)(enc + ((size_t)(s0 + warp) * BATCH + b) * H2);
        #pragma unroll
        for (int i = 0; i < 16; i++) va[i] = row[lane + 32 * i];
    }

    for (int s = s0 + warp; s < s1; s += 8) {
        {   // prefetch s+4 while processing s
            const float4* row = (const float4*)(enc + ((size_t)(s + 4) * BATCH + b) * H2);
            #pragma unroll
            for (int i = 0; i < 16; i++) vb[i] = row[lane + 32 * i];
        }
        attn_step(w2v4, lane, va, hb, Zw, acc);
        if (s + 8 < s1) {   // prefetch s+8 while processing s+4
            const float4* row = (const float4*)(enc + ((size_t)(s + 8) * BATCH + b) * H2);
            #pragma unroll
            for (int i = 0; i < 16; i++) va[i] = row[lane + 32 * i];
        }
        attn_step(w2v4, lane, vb, hb, Zw, acc);
    }

    #pragma unroll
    for (int i = 0; i < 16; i++) {
        int c = 4 * (lane + 32 * i);
        atomicAdd(&s_acc[c + 0], acc[i].x);
        atomicAdd(&s_acc[c + 1], acc[i].y);
        atomicAdd(&s_acc[c + 2], acc[i].z);
        atomicAdd(&s_acc[c + 3], acc[i].w);
    }
    if (lane == 0) s_z[warp] = Zw;
    __syncthreads();

    float* dst = g_ctx_part + ((size_t)split * BATCH + b) * H2;
    for (int j = t; j < H2; j += 128) dst[j] = s_acc[j];
    if (t == 0) g_zpart[split * BATCH + b] = s_z[0] + s_z[1] + s_z[2] + s_z[3];
}

// ===========================================================================
// pack: merge split contexts, normalize, cvt fp16; append emb + hidden
// ===========================================================================
__global__ __launch_bounds__(256) void pack_kernel(
    const int* __restrict__ x, const float* __restrict__ emb_table,
    const float* __restrict__ hidden)
{
    int b = blockIdx.x, t = threadIdx.x;
    float z = g_zpart[b] + g_zpart[BATCH + b];
    float iz = 1.f / z;
    __half* dst = g_act16 + (size_t)b * KG;

    for (int f = 4 * t; f < H2; f += 1024) {
        float4 s = *(const float4*)(g_ctx_part + (size_t)b * H2 + f);
        float4 q = *(const float4*)(g_ctx_part + ((size_t)BATCH + b) * H2 + f);
        s.x += q.x; s.y += q.y; s.z += q.z; s.w += q.w;
        *(uint2*)(dst + f) = make_uint2(pk(s.x * iz, s.y * iz), pk(s.z * iz, s.w * iz));
    }
    int tok = x[b];
    for (int f = 4 * t; f < EMB; f += 1024) {
        float4 e = *(const float4*)(emb_table + (size_t)tok * EMB + f);
        *(uint2*)(dst + H2 + f) = make_uint2(pk(e.x, e.y), pk(e.z, e.w));
    }
    for (int f = 4 * t; f < HID; f += 1024) {
        float4 h = *(const float4*)(hidden + (size_t)b * HID + f);
        *(uint2*)(dst + K1G + f) = make_uint2(pk(h.x, h.y), pk(h.z, h.w));
    }
}

// ===========================================================================
// fp16 GEMM (R10-frozen): tile M128 x N128, K-chunk 32, cp.async 3-stage /
// 2-ahead pipeline (one sync per chunk), 2 CTAs/SM.
// ===========================================================================
extern __shared__ char smg[];

__global__ __launch_bounds__(256, 2) void gemm_kernel(
    int mode,
    const float* __restrict__ W_ih, const float* __restrict__ W_hh,
    const float* __restrict__ W_fc, const float* __restrict__ b_fc,
    float* __restrict__ pred)
{
    __shared__ float s_bias[128];

    int t = threadIdx.x, warp = t >> 5, lane = t & 31;
    int nt = blockIdx.x, split = blockIdx.y;

    const __half* Aact = (mode == 0) ? g_act16 : g_h16;
    int lda   = (mode == 0) ? KG : HID;
    int Kbase = (mode == 0) ? split * (KG / GSPLIT) : 0;
    int NC    = (mode == 0) ? (KG / GSPLIT) >> 5 : HID >> 5;

    if (mode == 1 && t < 128) s_bias[t] = b_fc[nt * 128 + t];

    float acc[4][4][4];
    #pragma unroll
    for (int mi = 0; mi < 4; mi++)
        #pragma unroll
        for (int ni = 0; ni < 4; ni++)
            #pragma unroll
            for (int q = 0; q < 4; q++) acc[mi][ni][q] = 0.f;

    uint32_t sb = smem_u32(smg);

    auto issue_chunk = [&](int ch) {
        int stg = ch % DEPTH;
        int k0 = Kbase + (ch << 5);
        uint32_t abase = sb + stg * STG_B;
        uint32_t bbase = abase + A_STG_B;
        #pragma unroll
        for (int j = 0; j < 2; j++) {
            int id = t + j * 256;
            int row = id >> 2, seg = id & 3;
            cpa16(abase + row * (PADA * 2) + seg * 16,
                  Aact + (size_t)row * lda + k0 + seg * 8);
        }
        const float* wb;
        int ldb, koff;
        if (mode == 0) {
            if (k0 < K1G) { wb = W_ih; ldb = K1G; koff = k0; }
            else          { wb = W_hh; ldb = HID; koff = k0 - K1G; }
        } else            { wb = W_fc; ldb = HID; koff = k0; }
        #pragma unroll
        for (int j = 0; j < 4; j++) {
            int id = t + j * 256;
            int row = id >> 3, seg = id & 7;
            cpa16(bbase + row * (PADB * 4) + seg * 16,
                  wb + (size_t)(nt * 128 + row) * ldb + koff + seg * 4);
        }
        CPA_COMMIT();
    };

    int mw = (warp >> 2) * 64, nw = (warp & 3) * 32;

    auto mma_stage = [&](int stg) {
        const __half* As = (const __half*)(smg + stg * STG_B);
        const float*  Bs = (const float*)(smg + stg * STG_B + A_STG_B);
        #pragma unroll
        for (int ks = 0; ks < 2; ks++) {
            uint32_t ah[4][4];
            int ar = mw + (lane & 15);
            int ac = ks * 16 + (lane >> 4) * 8;
            #pragma unroll
            for (int mi = 0; mi < 4; mi++)
                ldm_x4(ah[mi], &As[(ar + mi * 16) * PADA + ac]);
            int nb = nw + (lane >> 2);
            int kk = ks * 16 + (lane & 3) * 2;
            #pragma unroll
            for (int ni = 0; ni < 4; ni++) {
                const float* bp = &Bs[(nb + ni * 8) * PADB + kk];
                float2 lo = *(const float2*)bp;
                float2 hi = *(const float2*)(bp + 8);
                uint32_t bb[2] = { pk(lo.x, lo.y), pk(hi.x, hi.y) };
                #pragma unroll
                for (int mi = 0; mi < 4; mi++)
                    mma_f16(acc[mi][ni], ah[mi], bb);
            }
        }
    };

    issue_chunk(0);
    issue_chunk(1);

    for (int ch = 0; ch < NC; ch++) {
        CPA_WAIT(1);
        __syncthreads();
        if (ch + 2 < NC) issue_chunk(ch + 2);
        else             CPA_COMMIT();
        mma_stage(ch % DEPTH);
    }

    int r0 = mw + (lane >> 2);
    int cb = nw + (lane & 3) * 2;
    if (mode == 0) {
        float* Cp = g_gates_part + (size_t)split * BATCH * NG;
        #pragma unroll
        for (int mi = 0; mi < 4; mi++)
            #pragma unroll
            for (int ni = 0; ni < 4; ni++) {
                int ng0 = nt * 128 + cb + ni * 8;
                int rA  = r0 + mi * 16;
                Cp[(size_t)rA * NG + ng0]           = acc[mi][ni][0];
                Cp[(size_t)rA * NG + ng0 + 1]       = acc[mi][ni][1];
                Cp[(size_t)(rA + 8) * NG + ng0]     = acc[mi][ni][2];
                Cp[(size_t)(rA + 8) * NG + ng0 + 1] = acc[mi][ni][3];
            }
    } else {
        #pragma unroll
        for (int mi = 0; mi < 4; mi++)
            #pragma unroll
            for (int ni = 0; ni < 4; ni++) {
                int c0 = cb + ni * 8;
                int ng0 = nt * 128 + c0;
                int rA  = r0 + mi * 16;
                float b0 = s_bias[c0], b1 = s_bias[c0 + 1];
                pred[(size_t)rA * VOCAB + ng0]           = acc[mi][ni][0] + b0;
                pred[(size_t)rA * VOCAB + ng0 + 1]       = acc[mi][ni][1] + b1;
                pred[(size_t)(rA + 8) * VOCAB + ng0]     = acc[mi][ni][2] + b0;
                pred[(size_t)(rA + 8) * VOCAB + ng0 + 1] = acc[mi][ni][3] + b1;
            }
    }
}

// ===========================================================================
// LSTM pointwise: sum split-K gate partials + biases -> h_new (fp32+fp16), c_new
// ===========================================================================
__device__ __forceinline__ float sigmf(float v) { return 1.f / (1.f + __expf(-v)); }
__device__ __forceinline__ float tanhfast(float v) { return 1.f - 2.f / (1.f + __expf(2.f * v)); }

__global__ __launch_bounds__(256) void lstm_kernel(
    const float* __restrict__ b_ih, const float* __restrict__ b_hh,
    const float* __restrict__ cell, float* __restrict__ h_out, float* __restrict__ c_out)
{
    int idx = blockIdx.x * 256 + threadIdx.x;
    int b = idx >> 10, j = idx & 1023;
    const float* g = g_gates_part + (size_t)b * NG;
    float gs[4];
    #pragma unroll
    for (int gi = 0; gi < 4; gi++) {
        int col = gi * HID + j;
        float v = b_ih[col] + b_hh[col];
        #pragma unroll
        for (int y = 0; y < GSPLIT; y++) v += g[(size_t)y * BATCH * NG + col];
        gs[gi] = v;
    }
    float ig = sigmf(gs[0]), fg = sigmf(gs[1]);
    float gg = tanhfast(gs[2]), og = sigmf(gs[3]);
    float c = fg * cell[idx] + ig * gg;
    float h = og * tanhfast(c);
    c_out[idx] = c;
    h_out[idx] = h;
    g_h16[idx] = __float2half(h);
}

// ===========================================================================
extern "C" void kernel_launch(void* const* d_in, const int* in_sizes, int n_in,
                              void* d_out, int out_size)
{
    const int*   x      = (const int*)d_in[0];
    const float* enc    = (const float*)d_in[1];
    const float* hidden = (const float*)d_in[2];
    const float* cell   = (const float*)d_in[3];
    const float* emb    = (const float*)d_in[4];
    const float* W_e    = (const float*)d_in[5];
    const float* b_e    = (const float*)d_in[6];
    const float* W_ih   = (const float*)d_in[7];
    const float* W_hh   = (const float*)d_in[8];
    const float* b_ih   = (const float*)d_in[9];
    const float* b_hh   = (const float*)d_in[10];
    const float* W_fc   = (const float*)d_in[11];
    const float* b_fc   = (const float*)d_in[12];

    float* out   = (float*)d_out;
    float* h_out = out + (size_t)BATCH * VOCAB;
    float* c_out = h_out + BATCH * HID;

    static bool attr_set = false;
    if (!attr_set) {
        cudaFuncSetAttribute(gemm_kernel, cudaFuncAttributeMaxDynamicSharedMemorySize,
                             GEMM_SMEM);
        attr_set = true;
    }

    attn_kernel<<<dim3(BATCH, ASPL), 128>>>(enc, hidden, W_e, b_e);
    pack_kernel<<<BATCH, 256>>>(x, emb, hidden);
    gemm_kernel<<<dim3(NG / 128, GSPLIT), 256, GEMM_SMEM>>>(
        0, W_ih, W_hh, W_fc, b_fc, out);
    lstm_kernel<<<(BATCH * HID) / 256, 256>>>(b_ih, b_hh, cell, h_out, c_out);
    gemm_kernel<<<dim3(VOCAB / 128, 1), 256, GEMM_SMEM>>>(
        1, W_ih, W_hh, W_fc, b_fc, out);
}

// round 13
// speedup vs baseline: 1.1542x; 1.1542x over previous
#include <cuda_runtime.h>
#include <cuda_fp16.h>
#include <cstdint>

#define BATCH 128
#define SEQ   512
#define HID   1024
#define H2    2048
#define EMB   512
#define VOCAB 32000
#define KG    3584          /* 2048 ctx + 512 emb + 1024 hidden */
#define NG    4096
#define K1G   2560          /* W_ih K extent */
#define GSPLIT 8
#define PADA  40
#define PADB  40
#define DEPTH 3
#define A_STG_B (128 * PADA * 2)
#define B_STG_B (128 * PADB * 4)
#define STG_B   (A_STG_B + B_STG_B)
#define GEMM_SMEM (DEPTH * STG_B)           /* 92160 -> 2 CTAs/SM */

__device__ __half g_act16[BATCH * KG];      // fp16 [ctx | emb | hidden]
__device__ __half g_h16[BATCH * HID];       // fp16 h_new
__device__ float  g_gates_part[GSPLIT * BATCH * NG];

// ---------------------------------------------------------------------------
__device__ __forceinline__ uint32_t smem_u32(const void* p) {
    return (uint32_t)__cvta_generic_to_shared(p);
}
__device__ __forceinline__ void cpa16(uint32_t dst, const void* src) {
    asm volatile("cp.async.cg.shared.global [%0], [%1], 16;\n" :: "r"(dst), "l"(src));
}
#define CPA_COMMIT() asm volatile("cp.async.commit_group;\n" ::: "memory")
#define CPA_WAIT(n)  asm volatile("cp.async.wait_group %0;\n" :: "n"(n) : "memory")

__device__ __forceinline__ void ldm_x4(uint32_t* r, const __half* p) {
    uint32_t a = smem_u32(p);
    asm volatile("ldmatrix.sync.aligned.m8n8.x4.shared.b16 {%0,%1,%2,%3}, [%4];\n"
                 : "=r"(r[0]), "=r"(r[1]), "=r"(r[2]), "=r"(r[3]) : "r"(a));
}
__device__ __forceinline__ void mma_f16(float* d, const uint32_t* a, const uint32_t* b) {
    asm volatile("mma.sync.aligned.m16n8k16.row.col.f32.f16.f16.f32 "
                 "{%0,%1,%2,%3}, {%4,%5,%6,%7}, {%8,%9}, {%0,%1,%2,%3};\n"
                 : "+f"(d[0]), "+f"(d[1]), "+f"(d[2]), "+f"(d[3])
                 : "r"(a[0]), "r"(a[1]), "r"(a[2]), "r"(a[3]), "r"(b[0]), "r"(b[1]));
}
__device__ __forceinline__ uint32_t pk(float a, float b) {
    __half2 h = __floats2half2_rn(a, b);
    return *reinterpret_cast<uint32_t*>(&h);
}

// ===========================================================================
// attention: 1 CTA / batch elem, 512 threads (16 warps), warp-PAIR feature
// split: warp w handles features [0,1024), warp w+8 handles [1024,2048) of
// the SAME rows (pair p = w&7 owns rows p, p+8, ...). Half-dots exchanged
// via smem + 2-warp named barrier (parity double-buffered). No max-shift
// (energies relu-bounded -> exp safe). Writes fp16 [ctx | emb | hidden].
// ===========================================================================
__global__ __launch_bounds__(512) void attn_kernel(
    const float* __restrict__ enc, const float* __restrict__ hidden,
    const float* __restrict__ W_e, const float* __restrict__ b_e,
    const int* __restrict__ x, const float* __restrict__ emb_table)
{
    __shared__ float s_w2[H2], s_acc[H2];
    __shared__ float s_red[16], s_z[8];
    __shared__ float s_pr[2][8][2];
    __shared__ float s_hb, s_invZ;

    int b = blockIdx.x, t = threadIdx.x;
    int warp = t >> 5, lane = t & 31;
    int pair = warp & 7, half = warp >> 3;   // warps 0-7: half 0; 8-15: half 1
    int barid = 1 + pair;

    for (int j = t; j < H2; j += 512) { s_w2[j] = W_e[HID + j]; s_acc[j] = 0.f; }

    // hb = hidden[b] . W_e[0:HID] + b_e
    float p = 0.f;
    for (int j = t; j < HID; j += 512) p += hidden[b * HID + j] * W_e[j];
    #pragma unroll
    for (int o = 16; o > 0; o >>= 1) p += __shfl_xor_sync(0xffffffffu, p, o);
    if (lane == 0) s_red[warp] = p;
    __syncthreads();
    if (t == 0) {
        float s = 0.f;
        #pragma unroll
        for (int i = 0; i < 16; i++) s += s_red[i];
        s_hb = s + b_e[0];
    }
    __syncthreads();
    float hb = s_hb;

    // this warp's half of w2, lane-strided float4 view
    const float4* w2p = ((const float4*)s_w2) + half * 256 + lane;

    float4 acc[8];
    #pragma unroll
    for (int i = 0; i < 8; i++) acc[i] = make_float4(0.f, 0.f, 0.f, 0.f);
    float Zw = 0.f;

    float4 va[8], vb[8];

    auto rowp = [&](int s) {
        return ((const float4*)(enc + ((size_t)s * BATCH + b) * H2)) + half * 256 + lane;
    };

    // one step: half-dot, exchange with partner warp, wg, accumulate own half
    auto step = [&](const float4 v[8], int par) {
        float pr = 0.f;
        #pragma unroll
        for (int i = 0; i < 8; i++) {
            float4 w = w2p[32 * i];
            pr += v[i].x * w.x + v[i].y * w.y + v[i].z * w.z + v[i].w * w.w;
        }
        #pragma unroll
        for (int o = 16; o > 0; o >>= 1) pr += __shfl_xor_sync(0xffffffffu, pr, o);
        if (lane == 0) s_pr[par][pair][half] = pr;
        asm volatile("bar.sync %0, 64;" :: "r"(barid) : "memory");
        float e = s_pr[par][pair][0] + s_pr[par][pair][1] + hb;
        float wg = __expf(fmaxf(e, 0.f));
        if (half == 0) Zw += wg;
        #pragma unroll
        for (int i = 0; i < 8; i++) {
            acc[i].x += wg * v[i].x; acc[i].y += wg * v[i].y;
            acc[i].z += wg * v[i].z; acc[i].w += wg * v[i].w;
        }
    };

    {
        const float4* r0 = rowp(pair);
        #pragma unroll
        for (int i = 0; i < 8; i++) va[i] = r0[32 * i];
    }

    for (int s = pair; s < SEQ; s += 16) {
        {   // prefetch row s+8 while processing s
            const float4* r1 = rowp(s + 8);
            #pragma unroll
            for (int i = 0; i < 8; i++) vb[i] = r1[32 * i];
        }
        step(va, 0);
        if (s + 16 < SEQ) {   // prefetch s+16 while processing s+8
            const float4* r2 = rowp(s + 16);
            #pragma unroll
            for (int i = 0; i < 8; i++) va[i] = r2[32 * i];
        }
        step(vb, 1);
    }

    // merge: halves own disjoint features; pairs overlap -> smem atomics
    #pragma unroll
    for (int i = 0; i < 8; i++) {
        int c = 4 * (half * 256 + lane + 32 * i);
        atomicAdd(&s_acc[c + 0], acc[i].x);
        atomicAdd(&s_acc[c + 1], acc[i].y);
        atomicAdd(&s_acc[c + 2], acc[i].z);
        atomicAdd(&s_acc[c + 3], acc[i].w);
    }
    if (half == 0 && lane == 0) s_z[pair] = Zw;
    __syncthreads();
    if (t == 0) {
        float z = 0.f;
        #pragma unroll
        for (int i = 0; i < 8; i++) z += s_z[i];
        s_invZ = 1.f / z;
    }
    __syncthreads();
    float iz = s_invZ;

    __half* dst = g_act16 + (size_t)b * KG;
    for (int j = t; j < H2; j += 512) dst[j] = __float2half(s_acc[j] * iz);
    int tok = x[b];
    for (int j = t; j < EMB; j += 512)
        dst[H2 + j] = __float2half(emb_table[(size_t)tok * EMB + j]);
    for (int j = t; j < HID; j += 512)
        dst[K1G + j] = __float2half(hidden[b * HID + j]);
}

// ===========================================================================
// fp16 GEMM (R10-frozen): tile M128 x N128, K-chunk 32, cp.async 3-stage /
// 2-ahead pipeline (one sync per chunk), 2 CTAs/SM.
// ===========================================================================
extern __shared__ char smg[];

__global__ __launch_bounds__(256, 2) void gemm_kernel(
    int mode,
    const float* __restrict__ W_ih, const float* __restrict__ W_hh,
    const float* __restrict__ W_fc, const float* __restrict__ b_fc,
    float* __restrict__ pred)
{
    __shared__ float s_bias[128];

    int t = threadIdx.x, warp = t >> 5, lane = t & 31;
    int nt = blockIdx.x, split = blockIdx.y;

    const __half* Aact = (mode == 0) ? g_act16 : g_h16;
    int lda   = (mode == 0) ? KG : HID;
    int Kbase = (mode == 0) ? split * (KG / GSPLIT) : 0;
    int NC    = (mode == 0) ? (KG / GSPLIT) >> 5 : HID >> 5;

    if (mode == 1 && t < 128) s_bias[t] = b_fc[nt * 128 + t];

    float acc[4][4][4];
    #pragma unroll
    for (int mi = 0; mi < 4; mi++)
        #pragma unroll
        for (int ni = 0; ni < 4; ni++)
            #pragma unroll
            for (int q = 0; q < 4; q++) acc[mi][ni][q] = 0.f;

    uint32_t sb = smem_u32(smg);

    auto issue_chunk = [&](int ch) {
        int stg = ch % DEPTH;
        int k0 = Kbase + (ch << 5);
        uint32_t abase = sb + stg * STG_B;
        uint32_t bbase = abase + A_STG_B;
        #pragma unroll
        for (int j = 0; j < 2; j++) {
            int id = t + j * 256;
            int row = id >> 2, seg = id & 3;
            cpa16(abase + row * (PADA * 2) + seg * 16,
                  Aact + (size_t)row * lda + k0 + seg * 8);
        }
        const float* wb;
        int ldb, koff;
        if (mode == 0) {
            if (k0 < K1G) { wb = W_ih; ldb = K1G; koff = k0; }
            else          { wb = W_hh; ldb = HID; koff = k0 - K1G; }
        } else            { wb = W_fc; ldb = HID; koff = k0; }
        #pragma unroll
        for (int j = 0; j < 4; j++) {
            int id = t + j * 256;
            int row = id >> 3, seg = id & 7;
            cpa16(bbase + row * (PADB * 4) + seg * 16,
                  wb + (size_t)(nt * 128 + row) * ldb + koff + seg * 4);
        }
        CPA_COMMIT();
    };

    int mw = (warp >> 2) * 64, nw = (warp & 3) * 32;

    auto mma_stage = [&](int stg) {
        const __half* As = (const __half*)(smg + stg * STG_B);
        const float*  Bs = (const float*)(smg + stg * STG_B + A_STG_B);
        #pragma unroll
        for (int ks = 0; ks < 2; ks++) {
            uint32_t ah[4][4];
            int ar = mw + (lane & 15);
            int ac = ks * 16 + (lane >> 4) * 8;
            #pragma unroll
            for (int mi = 0; mi < 4; mi++)
                ldm_x4(ah[mi], &As[(ar + mi * 16) * PADA + ac]);
            int nb = nw + (lane >> 2);
            int kk = ks * 16 + (lane & 3) * 2;
            #pragma unroll
            for (int ni = 0; ni < 4; ni++) {
                const float* bp = &Bs[(nb + ni * 8) * PADB + kk];
                float2 lo = *(const float2*)bp;
                float2 hi = *(const float2*)(bp + 8);
                uint32_t bb[2] = { pk(lo.x, lo.y), pk(hi.x, hi.y) };
                #pragma unroll
                for (int mi = 0; mi < 4; mi++)
                    mma_f16(acc[mi][ni], ah[mi], bb);
            }
        }
    };

    issue_chunk(0);
    issue_chunk(1);

    for (int ch = 0; ch < NC; ch++) {
        CPA_WAIT(1);
        __syncthreads();
        if (ch + 2 < NC) issue_chunk(ch + 2);
        else             CPA_COMMIT();
        mma_stage(ch % DEPTH);
    }

    int r0 = mw + (lane >> 2);
    int cb = nw + (lane & 3) * 2;
    if (mode == 0) {
        float* Cp = g_gates_part + (size_t)split * BATCH * NG;
        #pragma unroll
        for (int mi = 0; mi < 4; mi++)
            #pragma unroll
            for (int ni = 0; ni < 4; ni++) {
                int ng0 = nt * 128 + cb + ni * 8;
                int rA  = r0 + mi * 16;
                Cp[(size_t)rA * NG + ng0]           = acc[mi][ni][0];
                Cp[(size_t)rA * NG + ng0 + 1]       = acc[mi][ni][1];
                Cp[(size_t)(rA + 8) * NG + ng0]     = acc[mi][ni][2];
                Cp[(size_t)(rA + 8) * NG + ng0 + 1] = acc[mi][ni][3];
            }
    } else {
        #pragma unroll
        for (int mi = 0; mi < 4; mi++)
            #pragma unroll
            for (int ni = 0; ni < 4; ni++) {
                int c0 = cb + ni * 8;
                int ng0 = nt * 128 + c0;
                int rA  = r0 + mi * 16;
                float b0 = s_bias[c0], b1 = s_bias[c0 + 1];
                pred[(size_t)rA * VOCAB + ng0]           = acc[mi][ni][0] + b0;
                pred[(size_t)rA * VOCAB + ng0 + 1]       = acc[mi][ni][1] + b1;
                pred[(size_t)(rA + 8) * VOCAB + ng0]     = acc[mi][ni][2] + b0;
                pred[(size_t)(rA + 8) * VOCAB + ng0 + 1] = acc[mi][ni][3] + b1;
            }
    }
}

// ===========================================================================
// LSTM pointwise: sum split-K gate partials + biases -> h_new (fp32+fp16), c_new
// ===========================================================================
__device__ __forceinline__ float sigmf(float v) { return 1.f / (1.f + __expf(-v)); }
__device__ __forceinline__ float tanhfast(float v) { return 1.f - 2.f / (1.f + __expf(2.f * v)); }

__global__ __launch_bounds__(256) void lstm_kernel(
    const float* __restrict__ b_ih, const float* __restrict__ b_hh,
    const float* __restrict__ cell, float* __restrict__ h_out, float* __restrict__ c_out)
{
    int idx = blockIdx.x * 256 + threadIdx.x;
    int b = idx >> 10, j = idx & 1023;
    const float* g = g_gates_part + (size_t)b * NG;
    float gs[4];
    #pragma unroll
    for (int gi = 0; gi < 4; gi++) {
        int col = gi * HID + j;
        float v = b_ih[col] + b_hh[col];
        #pragma unroll
        for (int y = 0; y < GSPLIT; y++) v += g[(size_t)y * BATCH * NG + col];
        gs[gi] = v;
    }
    float ig = sigmf(gs[0]), fg = sigmf(gs[1]);
    float gg = tanhfast(gs[2]), og = sigmf(gs[3]);
    float c = fg * cell[idx] + ig * gg;
    float h = og * tanhfast(c);
    c_out[idx] = c;
    h_out[idx] = h;
    g_h16[idx] = __float2half(h);
}

// ===========================================================================
extern "C" void kernel_launch(void* const* d_in, const int* in_sizes, int n_in,
                              void* d_out, int out_size)
{
    const int*   x      = (const int*)d_in[0];
    const float* enc    = (const float*)d_in[1];
    const float* hidden = (const float*)d_in[2];
    const float* cell   = (const float*)d_in[3];
    const float* emb    = (const float*)d_in[4];
    const float* W_e    = (const float*)d_in[5];
    const float* b_e    = (const float*)d_in[6];
    const float* W_ih   = (const float*)d_in[7];
    const float* W_hh   = (const float*)d_in[8];
    const float* b_ih   = (const float*)d_in[9];
    const float* b_hh   = (const float*)d_in[10];
    const float* W_fc   = (const float*)d_in[11];
    const float* b_fc   = (const float*)d_in[12];

    float* out   = (float*)d_out;
    float* h_out = out + (size_t)BATCH * VOCAB;
    float* c_out = h_out + BATCH * HID;

    static bool attr_set = false;
    if (!attr_set) {
        cudaFuncSetAttribute(gemm_kernel, cudaFuncAttributeMaxDynamicSharedMemorySize,
                             GEMM_SMEM);
        attr_set = true;
    }

    attn_kernel<<<BATCH, 512>>>(enc, hidden, W_e, b_e, x, emb);
    gemm_kernel<<<dim3(NG / 128, GSPLIT), 256, GEMM_SMEM>>>(
        0, W_ih, W_hh, W_fc, b_fc, out);
    lstm_kernel<<<(BATCH * HID) / 256, 256>>>(b_ih, b_hh, cell, h_out, c_out);
    gemm_kernel<<<dim3(VOCAB / 128, 1), 256, GEMM_SMEM>>>(
        1, W_ih, W_hh, W_fc, b_fc, out);
}